// round 1
// baseline (speedup 1.0000x reference)
#include <cuda_runtime.h>
#include <math.h>

#define B_ 4
#define T_ 4096
#define C_ 768
#define H_ 64
#define BM 64
#define BN 64
#define NT (T_/BM)     // 64 q-tiles
#define PAD 68

// scratch for Q,K,V projections (4 MB each)
__device__ float g_Q[B_*T_*H_];
__device__ float g_K[B_*T_*H_];
__device__ float g_V[B_*T_*H_];

// ---------------------------------------------------------------------------
// QKV projection: one block = 64 rows of x; thread (rgrp,h) computes 16 rows
// for one h column of all three matrices.  x chunk cached in SMEM (broadcast
// reads), W streamed through L1.
// ---------------------------------------------------------------------------
__global__ __launch_bounds__(256) void qkv_kernel(
    const float* __restrict__ x,
    const float* __restrict__ Wq,
    const float* __restrict__ Wk,
    const float* __restrict__ Wv)
{
    __shared__ float xs[64*128];
    const int tid  = threadIdx.x;
    const int h    = tid & 63;
    const int rbase = (tid >> 6) << 4;       // 0,16,32,48
    const long row0 = (long)blockIdx.x * 64;

    float aq[16], ak[16], av[16];
#pragma unroll
    for (int i = 0; i < 16; i++) { aq[i] = 0.f; ak[i] = 0.f; av[i] = 0.f; }

    for (int c0 = 0; c0 < C_; c0 += 128) {
#pragma unroll
        for (int t = 0; t < 8; t++) {
            int idx4 = tid + t*256;          // 2048 float4 = 64x128 floats
            int r  = idx4 >> 5;
            int c4 = idx4 & 31;
            float4 v = *(const float4*)(x + (row0 + r)*C_ + c0 + (c4 << 2));
            *(float4*)(xs + r*128 + (c4 << 2)) = v;
        }
        __syncthreads();
#pragma unroll 4
        for (int c = 0; c < 128; c++) {
            float wq = Wq[(c0 + c)*H_ + h];
            float wk = Wk[(c0 + c)*H_ + h];
            float wv = Wv[(c0 + c)*H_ + h];
#pragma unroll
            for (int i = 0; i < 16; i++) {
                float xv = xs[(rbase + i)*128 + c];
                aq[i] = fmaf(xv, wq, aq[i]);
                ak[i] = fmaf(xv, wk, ak[i]);
                av[i] = fmaf(xv, wv, av[i]);
            }
        }
        __syncthreads();
    }
#pragma unroll
    for (int i = 0; i < 16; i++) {
        long r = row0 + rbase + i;
        g_Q[r*H_ + h] = aq[i];
        g_K[r*H_ + h] = ak[i];
        g_V[r*H_ + h] = av[i];
    }
}

// ---------------------------------------------------------------------------
// Flash attention, causal.  Block = 256 threads as 16x16; thread owns a 4x4
// S-tile / O-tile.  Softmax state (m,l) lives in registers, reduced across
// the 16 tx-lanes with shfl.  Each block processes q-tile pair (i, 63-i) so
// all 128 blocks do exactly 65 k-tiles (balanced single wave on 148 SMs).
// ---------------------------------------------------------------------------
__global__ __launch_bounds__(256) void flash_kernel(float* __restrict__ out)
{
    extern __shared__ float sm[];
    float* Qs = sm;                 // [BM][PAD]  natural  [r][h]
    float* Kt = sm +   BM*PAD;      // [H_][PAD]  transposed [h][c]
    float* Vs = sm + 2*BM*PAD;      // [BN][PAD]  natural  [k][h]
    float* Ps = sm + 3*BM*PAD;      // [BM][PAD]  probabilities

    const int tid = threadIdx.x;
    const int tx  = tid & 15;
    const int ty  = tid >> 4;
    const int b   = blockIdx.y;
    const float scale = rsqrtf((float)C_);

    const float* Qg = g_Q + (long)b*T_*H_;
    const float* Kg = g_K + (long)b*T_*H_;
    const float* Vg = g_V + (long)b*T_*H_;

    for (int rep = 0; rep < 2; rep++) {
        const int qt = rep ? (NT - 1 - (int)blockIdx.x) : (int)blockIdx.x;
        const int q0 = qt * BM;

        // load Q tile (scale folded in)
#pragma unroll
        for (int t = 0; t < 4; t++) {
            int idx4 = tid + t*256;          // 1024 float4
            int r  = idx4 >> 4;
            int h4 = (idx4 & 15) << 2;
            float4 v = *(const float4*)(Qg + (long)(q0 + r)*H_ + h4);
            v.x *= scale; v.y *= scale; v.z *= scale; v.w *= scale;
            *(float4*)(Qs + r*PAD + h4) = v;
        }

        float m[4], l[4], acc[4][4];
#pragma unroll
        for (int i = 0; i < 4; i++) {
            m[i] = -INFINITY; l[i] = 0.f;
#pragma unroll
            for (int j = 0; j < 4; j++) acc[i][j] = 0.f;
        }

        for (int kt = 0; kt <= qt; kt++) {
            const int k0 = kt * BN;

            // load K (transposed into [h][c]) and V (natural)
#pragma unroll
            for (int t = 0; t < 4; t++) {
                int idx4 = tid + t*256;
                int c  = idx4 >> 4;
                int h4 = (idx4 & 15) << 2;
                float4 kv = *(const float4*)(Kg + (long)(k0 + c)*H_ + h4);
                Kt[(h4 + 0)*PAD + c] = kv.x;
                Kt[(h4 + 1)*PAD + c] = kv.y;
                Kt[(h4 + 2)*PAD + c] = kv.z;
                Kt[(h4 + 3)*PAD + c] = kv.w;
                float4 vv = *(const float4*)(Vg + (long)(k0 + c)*H_ + h4);
                *(float4*)(Vs + c*PAD + h4) = vv;
            }
            __syncthreads();

            // ---- phase 1: S = Q K^T (register 4x4 tile) ----
            float s[4][4];
#pragma unroll
            for (int i = 0; i < 4; i++)
#pragma unroll
                for (int j = 0; j < 4; j++) s[i][j] = 0.f;

#pragma unroll 4
            for (int h0 = 0; h0 < H_; h0 += 4) {
                float qf[4][4], kf[4][4];
#pragma unroll
                for (int i = 0; i < 4; i++) {
                    float4 q4 = *(const float4*)(Qs + (ty*4 + i)*PAD + h0);
                    qf[i][0] = q4.x; qf[i][1] = q4.y; qf[i][2] = q4.z; qf[i][3] = q4.w;
                }
#pragma unroll
                for (int u = 0; u < 4; u++) {
                    float4 k4 = *(const float4*)(Kt + (h0 + u)*PAD + tx*4);
                    kf[u][0] = k4.x; kf[u][1] = k4.y; kf[u][2] = k4.z; kf[u][3] = k4.w;
                }
#pragma unroll
                for (int i = 0; i < 4; i++)
#pragma unroll
                    for (int j = 0; j < 4; j++) {
                        s[i][j] = fmaf(qf[i][0], kf[0][j], s[i][j]);
                        s[i][j] = fmaf(qf[i][1], kf[1][j], s[i][j]);
                        s[i][j] = fmaf(qf[i][2], kf[2][j], s[i][j]);
                        s[i][j] = fmaf(qf[i][3], kf[3][j], s[i][j]);
                    }
            }

            // causal mask on the diagonal tile
            if (kt == qt) {
#pragma unroll
                for (int i = 0; i < 4; i++)
#pragma unroll
                    for (int j = 0; j < 4; j++)
                        if (k0 + tx*4 + j > q0 + ty*4 + i) s[i][j] = -INFINITY;
            }

            // ---- phase 2: online softmax, all in registers ----
#pragma unroll
            for (int i = 0; i < 4; i++) {
                float tm = fmaxf(fmaxf(s[i][0], s[i][1]), fmaxf(s[i][2], s[i][3]));
#pragma unroll
                for (int w = 1; w < 16; w <<= 1)
                    tm = fmaxf(tm, __shfl_xor_sync(0xffffffffu, tm, w));
                float mn    = fmaxf(m[i], tm);
                float alpha = __expf(m[i] - mn);
                m[i] = mn;
                float rs = 0.f;
#pragma unroll
                for (int j = 0; j < 4; j++) {
                    float p = __expf(s[i][j] - mn);
                    s[i][j] = p;
                    rs += p;
                }
#pragma unroll
                for (int w = 1; w < 16; w <<= 1)
                    rs += __shfl_xor_sync(0xffffffffu, rs, w);
                l[i] = l[i]*alpha + rs;
#pragma unroll
                for (int j = 0; j < 4; j++) acc[i][j] *= alpha;
                float4 p4 = make_float4(s[i][0], s[i][1], s[i][2], s[i][3]);
                *(float4*)(Ps + (ty*4 + i)*PAD + tx*4) = p4;
            }
            __syncthreads();

            // ---- phase 3: O += P V ----
#pragma unroll 4
            for (int k04 = 0; k04 < BN; k04 += 4) {
                float pf[4][4], vf[4][4];
#pragma unroll
                for (int i = 0; i < 4; i++) {
                    float4 p4 = *(const float4*)(Ps + (ty*4 + i)*PAD + k04);
                    pf[i][0] = p4.x; pf[i][1] = p4.y; pf[i][2] = p4.z; pf[i][3] = p4.w;
                }
#pragma unroll
                for (int u = 0; u < 4; u++) {
                    float4 v4 = *(const float4*)(Vs + (k04 + u)*PAD + tx*4);
                    vf[u][0] = v4.x; vf[u][1] = v4.y; vf[u][2] = v4.z; vf[u][3] = v4.w;
                }
#pragma unroll
                for (int i = 0; i < 4; i++)
#pragma unroll
                    for (int j = 0; j < 4; j++) {
                        acc[i][j] = fmaf(pf[i][0], vf[0][j], acc[i][j]);
                        acc[i][j] = fmaf(pf[i][1], vf[1][j], acc[i][j]);
                        acc[i][j] = fmaf(pf[i][2], vf[2][j], acc[i][j]);
                        acc[i][j] = fmaf(pf[i][3], vf[3][j], acc[i][j]);
                    }
            }
            __syncthreads();
        } // kt

        // finalize: O = acc / l
#pragma unroll
        for (int i = 0; i < 4; i++) {
            float inv = 1.f / l[i];
            float4 o = make_float4(acc[i][0]*inv, acc[i][1]*inv,
                                   acc[i][2]*inv, acc[i][3]*inv);
            *(float4*)(out + ((long)b*T_ + q0 + ty*4 + i)*H_ + tx*4) = o;
        }
    } // rep
}

// ---------------------------------------------------------------------------
extern "C" void kernel_launch(void* const* d_in, const int* in_sizes, int n_in,
                              void* d_out, int out_size)
{
    const float* x  = (const float*)d_in[0];
    const float* Wq = (const float*)d_in[1];
    const float* Wk = (const float*)d_in[2];
    const float* Wv = (const float*)d_in[3];
    float* out = (float*)d_out;

    qkv_kernel<<<(B_*T_)/64, 256>>>(x, Wq, Wk, Wv);

    const int smem_bytes = 4*BM*PAD*(int)sizeof(float);   // 69632 B
    cudaFuncSetAttribute(flash_kernel,
                         cudaFuncAttributeMaxDynamicSharedMemorySize, smem_bytes);
    dim3 grid(NT/2, B_);
    flash_kernel<<<grid, 256, smem_bytes>>>(out);
}

// round 2
// speedup vs baseline: 1.4446x; 1.4446x over previous
#include <cuda_runtime.h>
#include <math.h>
#include <stdint.h>

#define B_ 4
#define T_ 4096
#define C_ 768
#define H_ 64
#define PAD 72          // 72 mod 32 = 8 -> all frag LDS patterns (8g+q) conflict-free

// scratch for Q,K,V projections (4 MB each)
__device__ float g_Q[B_*T_*H_];
__device__ float g_K[B_*T_*H_];
__device__ float g_V[B_*T_*H_];

__device__ __forceinline__ uint32_t f2tf32(float f) {
    uint32_t u;
    asm("cvt.rna.tf32.f32 %0, %1;" : "=r"(u) : "f"(f));
    return u;
}

__device__ __forceinline__ void mma_tf32(float d[4],
    uint32_t a0, uint32_t a1, uint32_t a2, uint32_t a3,
    uint32_t b0, uint32_t b1)
{
    asm volatile(
        "mma.sync.aligned.m16n8k8.row.col.f32.tf32.tf32.f32 "
        "{%0,%1,%2,%3}, {%4,%5,%6,%7}, {%8,%9}, {%0,%1,%2,%3};"
        : "+f"(d[0]), "+f"(d[1]), "+f"(d[2]), "+f"(d[3])
        : "r"(a0), "r"(a1), "r"(a2), "r"(a3), "r"(b0), "r"(b1));
}

// ---------------------------------------------------------------------------
// QKV projection (unchanged from R1): one block = 64 rows of x.
// ---------------------------------------------------------------------------
__global__ __launch_bounds__(256) void qkv_kernel(
    const float* __restrict__ x,
    const float* __restrict__ Wq,
    const float* __restrict__ Wk,
    const float* __restrict__ Wv)
{
    __shared__ float xs[64*128];
    const int tid  = threadIdx.x;
    const int h    = tid & 63;
    const int rbase = (tid >> 6) << 4;
    const long row0 = (long)blockIdx.x * 64;

    float aq[16], ak[16], av[16];
#pragma unroll
    for (int i = 0; i < 16; i++) { aq[i] = 0.f; ak[i] = 0.f; av[i] = 0.f; }

    for (int c0 = 0; c0 < C_; c0 += 128) {
#pragma unroll
        for (int t = 0; t < 8; t++) {
            int idx4 = tid + t*256;
            int r  = idx4 >> 5;
            int c4 = idx4 & 31;
            float4 v = *(const float4*)(x + (row0 + r)*C_ + c0 + (c4 << 2));
            *(float4*)(xs + r*128 + (c4 << 2)) = v;
        }
        __syncthreads();
#pragma unroll 4
        for (int c = 0; c < 128; c++) {
            float wq = Wq[(c0 + c)*H_ + h];
            float wk = Wk[(c0 + c)*H_ + h];
            float wv = Wv[(c0 + c)*H_ + h];
#pragma unroll
            for (int i = 0; i < 16; i++) {
                float xv = xs[(rbase + i)*128 + c];
                aq[i] = fmaf(xv, wq, aq[i]);
                ak[i] = fmaf(xv, wk, ak[i]);
                av[i] = fmaf(xv, wv, av[i]);
            }
        }
        __syncthreads();
    }
#pragma unroll
    for (int i = 0; i < 16; i++) {
        long r = row0 + rbase + i;
        g_Q[r*H_ + h] = aq[i];
        g_K[r*H_ + h] = ak[i];
        g_V[r*H_ + h] = av[i];
    }
}

// ---------------------------------------------------------------------------
// Flash attention with tf32 mma.sync (FA2 warp layout).
// 128 threads = 4 warps; warp w owns S/O rows [w*16, w*16+16).
// Each warp computes its full 16x64 S strip -> softmax is warp-local
// (quad shfl reductions); P goes through SMEM only for the D->A frag
// relayout (warp-private rows, so only __syncwarp needed).
// Grid: 64 q-tiles (descending work order) x 4 batches = 256 CTAs,
// 73.7KB smem -> 3 CTAs/SM.
// ---------------------------------------------------------------------------
__global__ __launch_bounds__(128) void flash_mma(float* __restrict__ out)
{
    extern __shared__ uint32_t smu[];
    uint32_t* Qs = smu;               // [64][PAD] tf32 (scale folded)
    uint32_t* Ks = smu + 64*PAD;      // [64][PAD] tf32, natural [key][h]
    uint32_t* Vs = smu + 2*64*PAD;    // [64][PAD] tf32, natural [key][h]
    uint32_t* Ps = smu + 3*64*PAD;    // [64][PAD] tf32 probabilities

    const int tid  = threadIdx.x;
    const int lane = tid & 31;
    const int warp = tid >> 5;
    const int g    = lane >> 2;       // group id (row within frag)
    const int q    = lane & 3;        // thread-in-group (col within frag)
    const int r0   = warp << 4;       // warp's first row
    const int b    = blockIdx.y;
    const int qt   = 63 - (int)blockIdx.x;   // big CTAs launch first
    const int q0   = qt << 6;
    const float scale = rsqrtf((float)C_);

    const float* Qg = g_Q + ((long)b*T_ + q0)*H_;
    const float* Kg = g_K + (long)b*T_*H_;
    const float* Vg = g_V + (long)b*T_*H_;

    // load Q tile (scaled, tf32)
#pragma unroll
    for (int t = 0; t < 8; t++) {
        int idx4 = tid + t*128;
        int r  = idx4 >> 4;
        int c4 = (idx4 & 15) << 2;
        float4 v = *(const float4*)(Qg + r*H_ + c4);
        Qs[r*PAD + c4 + 0] = f2tf32(v.x*scale);
        Qs[r*PAD + c4 + 1] = f2tf32(v.y*scale);
        Qs[r*PAD + c4 + 2] = f2tf32(v.z*scale);
        Qs[r*PAD + c4 + 3] = f2tf32(v.w*scale);
    }

    float o[8][4];
#pragma unroll
    for (int j = 0; j < 8; j++) { o[j][0]=0.f; o[j][1]=0.f; o[j][2]=0.f; o[j][3]=0.f; }
    float m0 = -INFINITY, m1 = -INFINITY, l0 = 0.f, l1 = 0.f;

    for (int kt = 0; kt <= qt; kt++) {
        const int k0 = kt << 6;

        // load K,V tiles (tf32)
#pragma unroll
        for (int t = 0; t < 8; t++) {
            int idx4 = tid + t*128;
            int r  = idx4 >> 4;
            int c4 = (idx4 & 15) << 2;
            float4 kv = *(const float4*)(Kg + (long)(k0 + r)*H_ + c4);
            Ks[r*PAD + c4 + 0] = f2tf32(kv.x);
            Ks[r*PAD + c4 + 1] = f2tf32(kv.y);
            Ks[r*PAD + c4 + 2] = f2tf32(kv.z);
            Ks[r*PAD + c4 + 3] = f2tf32(kv.w);
            float4 vv = *(const float4*)(Vg + (long)(k0 + r)*H_ + c4);
            Vs[r*PAD + c4 + 0] = f2tf32(vv.x);
            Vs[r*PAD + c4 + 1] = f2tf32(vv.y);
            Vs[r*PAD + c4 + 2] = f2tf32(vv.z);
            Vs[r*PAD + c4 + 3] = f2tf32(vv.w);
        }
        __syncthreads();

        // ---- phase 1: S = Q K^T ----
        float s[8][4];
#pragma unroll
        for (int j = 0; j < 8; j++) { s[j][0]=0.f; s[j][1]=0.f; s[j][2]=0.f; s[j][3]=0.f; }

#pragma unroll
        for (int h0 = 0; h0 < H_; h0 += 8) {
            uint32_t a0 = Qs[(r0+g  )*PAD + h0 + q    ];
            uint32_t a1 = Qs[(r0+g+8)*PAD + h0 + q    ];
            uint32_t a2 = Qs[(r0+g  )*PAD + h0 + q + 4];
            uint32_t a3 = Qs[(r0+g+8)*PAD + h0 + q + 4];
#pragma unroll
            for (int j = 0; j < 8; j++) {
                uint32_t b0 = Ks[(j*8+g)*PAD + h0 + q    ];
                uint32_t b1 = Ks[(j*8+g)*PAD + h0 + q + 4];
                mma_tf32(s[j], a0, a1, a2, a3, b0, b1);
            }
        }

        // causal mask on the diagonal tile (q0 == k0 -> local compare)
        if (kt == qt) {
#pragma unroll
            for (int j = 0; j < 8; j++) {
                int c0 = j*8 + 2*q, c1 = c0 + 1;
                int ra = r0 + g,    rb = ra + 8;
                if (c0 > ra) s[j][0] = -INFINITY;
                if (c1 > ra) s[j][1] = -INFINITY;
                if (c0 > rb) s[j][2] = -INFINITY;
                if (c1 > rb) s[j][3] = -INFINITY;
            }
        }

        // ---- phase 2: online softmax (warp-local, quad shfl) ----
        float tm0 = -INFINITY, tm1 = -INFINITY;
#pragma unroll
        for (int j = 0; j < 8; j++) {
            tm0 = fmaxf(tm0, fmaxf(s[j][0], s[j][1]));
            tm1 = fmaxf(tm1, fmaxf(s[j][2], s[j][3]));
        }
        tm0 = fmaxf(tm0, __shfl_xor_sync(0xffffffffu, tm0, 1));
        tm0 = fmaxf(tm0, __shfl_xor_sync(0xffffffffu, tm0, 2));
        tm1 = fmaxf(tm1, __shfl_xor_sync(0xffffffffu, tm1, 1));
        tm1 = fmaxf(tm1, __shfl_xor_sync(0xffffffffu, tm1, 2));

        float mn0 = fmaxf(m0, tm0), mn1 = fmaxf(m1, tm1);
        float al0 = __expf(m0 - mn0), al1 = __expf(m1 - mn1);
        m0 = mn0; m1 = mn1;

        float rs0 = 0.f, rs1 = 0.f;
#pragma unroll
        for (int j = 0; j < 8; j++) {
            float p0 = __expf(s[j][0] - mn0);
            float p1 = __expf(s[j][1] - mn0);
            float p2 = __expf(s[j][2] - mn1);
            float p3 = __expf(s[j][3] - mn1);
            rs0 += p0 + p1;
            rs1 += p2 + p3;
            int c = j*8 + 2*q;
            Ps[(r0+g  )*PAD + c    ] = f2tf32(p0);
            Ps[(r0+g  )*PAD + c + 1] = f2tf32(p1);
            Ps[(r0+g+8)*PAD + c    ] = f2tf32(p2);
            Ps[(r0+g+8)*PAD + c + 1] = f2tf32(p3);
        }
        rs0 += __shfl_xor_sync(0xffffffffu, rs0, 1);
        rs0 += __shfl_xor_sync(0xffffffffu, rs0, 2);
        rs1 += __shfl_xor_sync(0xffffffffu, rs1, 1);
        rs1 += __shfl_xor_sync(0xffffffffu, rs1, 2);
        l0 = l0*al0 + rs0;
        l1 = l1*al1 + rs1;

#pragma unroll
        for (int j = 0; j < 8; j++) {
            o[j][0] *= al0; o[j][1] *= al0;
            o[j][2] *= al1; o[j][3] *= al1;
        }
        __syncwarp();   // Ps rows are warp-private: warp-level visibility suffices

        // ---- phase 3: O += P V ----
#pragma unroll
        for (int kk = 0; kk < 64; kk += 8) {
            uint32_t a0 = Ps[(r0+g  )*PAD + kk + q    ];
            uint32_t a1 = Ps[(r0+g+8)*PAD + kk + q    ];
            uint32_t a2 = Ps[(r0+g  )*PAD + kk + q + 4];
            uint32_t a3 = Ps[(r0+g+8)*PAD + kk + q + 4];
#pragma unroll
            for (int j = 0; j < 8; j++) {
                uint32_t b0 = Vs[(kk+q  )*PAD + j*8 + g];
                uint32_t b1 = Vs[(kk+q+4)*PAD + j*8 + g];
                mma_tf32(o[j], a0, a1, a2, a3, b0, b1);
            }
        }
        __syncthreads();   // protect Ks/Vs before next tile's loads
    }

    // finalize: O = acc / l
    float inv0 = 1.f / l0, inv1 = 1.f / l1;
    float* outb = out + ((long)b*T_ + q0)*H_;
#pragma unroll
    for (int j = 0; j < 8; j++) {
        int c = j*8 + 2*q;
        float2 v0 = make_float2(o[j][0]*inv0, o[j][1]*inv0);
        float2 v1 = make_float2(o[j][2]*inv1, o[j][3]*inv1);
        *(float2*)(outb + (r0+g  )*H_ + c) = v0;
        *(float2*)(outb + (r0+g+8)*H_ + c) = v1;
    }
}

// ---------------------------------------------------------------------------
extern "C" void kernel_launch(void* const* d_in, const int* in_sizes, int n_in,
                              void* d_out, int out_size)
{
    const float* x  = (const float*)d_in[0];
    const float* Wq = (const float*)d_in[1];
    const float* Wk = (const float*)d_in[2];
    const float* Wv = (const float*)d_in[3];
    float* out = (float*)d_out;

    qkv_kernel<<<(B_*T_)/64, 256>>>(x, Wq, Wk, Wv);

    const int smem_bytes = 4*64*PAD*(int)sizeof(uint32_t);   // 73728 B
    cudaFuncSetAttribute(flash_mma,
                         cudaFuncAttributeMaxDynamicSharedMemorySize, smem_bytes);
    dim3 grid(T_/64, B_);   // 64 q-tiles (descending work) x 4 batches
    flash_mma<<<grid, 128, smem_bytes>>>(out);
}

// round 4
// speedup vs baseline: 3.0623x; 2.1199x over previous
#include <cuda_runtime.h>
#include <math.h>
#include <stdint.h>

#define B_ 4
#define T_ 4096
#define C_ 768
#define H_ 64

// Q,K,V stored as tf32 bit patterns (scale folded into Q)
__device__ __align__(16) unsigned g_Q[B_*T_*H_];
__device__ __align__(16) unsigned g_K[B_*T_*H_];
__device__ __align__(16) unsigned g_V[B_*T_*H_];
// W split into tf32 hi/lo for 3xTF32 projection: layout [3][C_][H_]
__device__ __align__(16) unsigned g_Whi[3*C_*H_];
__device__ __align__(16) unsigned g_Wlo[3*C_*H_];

__device__ __forceinline__ uint32_t f2tf32(float f) {
    uint32_t u;
    asm("cvt.rna.tf32.f32 %0, %1;" : "=r"(u) : "f"(f));
    return u;
}
__device__ __forceinline__ unsigned smaddr(const void* p) {
    unsigned a;
    asm("{.reg .u64 t; cvta.to.shared.u64 t, %1; cvt.u32.u64 %0, t;}" : "=r"(a) : "l"(p));
    return a;
}
#define CPA16(dst, src) asm volatile("cp.async.cg.shared.global [%0], [%1], 16;" :: "r"(dst), "l"(src))
#define CP_COMMIT()     asm volatile("cp.async.commit_group;")
#define CP_WAIT0()      asm volatile("cp.async.wait_group 0;" ::: "memory")

__device__ __forceinline__ void mma_tf32(float d[4],
    uint32_t a0, uint32_t a1, uint32_t a2, uint32_t a3,
    uint32_t b0, uint32_t b1)
{
    asm volatile(
        "mma.sync.aligned.m16n8k8.row.col.f32.tf32.tf32.f32 "
        "{%0,%1,%2,%3}, {%4,%5,%6,%7}, {%8,%9}, {%0,%1,%2,%3};"
        : "+f"(d[0]), "+f"(d[1]), "+f"(d[2]), "+f"(d[3])
        : "r"(a0), "r"(a1), "r"(a2), "r"(a3), "r"(b0), "r"(b1));
}

// ---------------------------------------------------------------------------
// Prep: split Wq|Wk|Wv into tf32 hi/lo (exact 3xTF32 decomposition).
// ---------------------------------------------------------------------------
__global__ __launch_bounds__(256) void wsplit_kernel(
    const float* __restrict__ Wq,
    const float* __restrict__ Wk,
    const float* __restrict__ Wv)
{
    int idx = blockIdx.x * 256 + threadIdx.x;          // 0 .. 3*C*H-1
    int mat = idx / (C_*H_);
    int rem = idx - mat*(C_*H_);
    const float* wp = (mat == 0) ? Wq : (mat == 1) ? Wk : Wv;
    float v = wp[rem];
    uint32_t hi = f2tf32(v);
    float lo = v - __uint_as_float(hi);
    g_Whi[idx] = hi;
    g_Wlo[idx] = f2tf32(lo);
}

// ---------------------------------------------------------------------------
// QKV projection as 3xTF32 MMA GEMM (fp32-accurate).
// CTA = 128 rows, 256 threads (8 warps); warp owns 16 rows x 192 cols.
// K=768 in 24 chunks of 32, double-buffered cp.async.
// W hi at cols [0,192), lo at [192,384), pitch 392 (=8 mod 32 -> b-frag
// bank 8q+g conflict-free).  x pitch 36 (a-frag bank 4g+q conflict-free);
// x split into hi/lo in registers (exact).
// ---------------------------------------------------------------------------
#define KC 32
#define NCH (C_/KC)       // 24
#define XP 36
#define WP 392
#define XS_SZ (128*XP)    // 4608 words/stage
#define WS_SZ (KC*WP)     // 12544 words/stage

__global__ __launch_bounds__(256) void qkv_mma(const float* __restrict__ x)
{
    extern __shared__ uint32_t sm[];
    uint32_t* xs = sm;                 // [2][128][XP]  raw fp32 bits
    uint32_t* ws = sm + 2*XS_SZ;       // [2][KC][WP]   tf32 hi|lo

    const int tid  = threadIdx.x;
    const int lane = tid & 31;
    const int warp = tid >> 5;
    const int g    = lane >> 2;
    const int q    = lane & 3;
    const int r0   = warp << 4;
    const long row0 = (long)blockIdx.x * 128;

    float acc[24][4];
#pragma unroll
    for (int nt = 0; nt < 24; nt++) { acc[nt][0]=0.f; acc[nt][1]=0.f; acc[nt][2]=0.f; acc[nt][3]=0.f; }

    auto issue = [&](int ch, int st) {
        const int c0 = ch * KC;
#pragma unroll
        for (int t = 0; t < 4; t++) {                  // x: 128x32 floats
            int idx4 = tid + t*256;
            int r  = idx4 >> 3;
            int c4 = (idx4 & 7) << 2;
            CPA16(smaddr(xs + st*XS_SZ + r*XP + c4),
                  x + (row0 + r)*C_ + c0 + c4);
        }
#pragma unroll
        for (int t = 0; t < 12; t++) {                 // W hi (6) + lo (6)
            int idx4 = tid + t*256;
            int isLo = idx4 >> 10;                     // 0 for first 1024, 1 after
            int rem1 = idx4 & 1023;
            int mat  = rem1 >> 9;                      // wait: 1024 float4 = 3*512?  (see below)
            // 3 mats x 32 k x 16 float4 = 1536 float4 per half; redo indexing:
            (void)isLo; (void)rem1; (void)mat;
        }
        // -- explicit W loop (3072 float4 total = 12 x 256) --
#pragma unroll
        for (int t = 0; t < 12; t++) {
            int idx4 = tid + t*256;                    // 0..3071
            int isLo = (idx4 >= 1536);
            int rr   = isLo ? idx4 - 1536 : idx4;      // 0..1535
            int mat  = rr >> 9;                        // /512
            int rem  = rr & 511;
            int k    = rem >> 4;
            int n4   = (rem & 15) << 2;
            const unsigned* src = (isLo ? g_Wlo : g_Whi) + (long)mat*C_*H_ + (long)(c0 + k)*H_ + n4;
            CPA16(smaddr(ws + st*WS_SZ + k*WP + isLo*192 + mat*64 + n4), src);
        }
    };

    issue(0, 0); CP_COMMIT();

    for (int ch = 0; ch < NCH; ch++) {
        const int st = ch & 1;
        CP_WAIT0();
        __syncthreads();
        if (ch + 1 < NCH) { issue(ch + 1, st ^ 1); CP_COMMIT(); }

        const uint32_t* xb = xs + st*XS_SZ;
        const uint32_t* wb = ws + st*WS_SZ;
#pragma unroll
        for (int ks = 0; ks < 4; ks++) {
            const int k0 = ks*8;
            float ar0 = __uint_as_float(xb[(r0+g  )*XP + k0 + q]);
            float ar1 = __uint_as_float(xb[(r0+g+8)*XP + k0 + q]);
            float ar2 = __uint_as_float(xb[(r0+g  )*XP + k0 + q + 4]);
            float ar3 = __uint_as_float(xb[(r0+g+8)*XP + k0 + q + 4]);
            uint32_t ah0 = f2tf32(ar0), ah1 = f2tf32(ar1), ah2 = f2tf32(ar2), ah3 = f2tf32(ar3);
            uint32_t al0 = f2tf32(ar0 - __uint_as_float(ah0));
            uint32_t al1 = f2tf32(ar1 - __uint_as_float(ah1));
            uint32_t al2 = f2tf32(ar2 - __uint_as_float(ah2));
            uint32_t al3 = f2tf32(ar3 - __uint_as_float(ah3));
#pragma unroll
            for (int nt = 0; nt < 24; nt++) {
                uint32_t bh0 = wb[(k0+q  )*WP + nt*8 + g];
                uint32_t bh1 = wb[(k0+q+4)*WP + nt*8 + g];
                uint32_t bl0 = wb[(k0+q  )*WP + 192 + nt*8 + g];
                uint32_t bl1 = wb[(k0+q+4)*WP + 192 + nt*8 + g];
                mma_tf32(acc[nt], ah0, ah1, ah2, ah3, bl0, bl1);
                mma_tf32(acc[nt], al0, al1, al2, al3, bh0, bh1);
                mma_tf32(acc[nt], ah0, ah1, ah2, ah3, bh0, bh1);
            }
        }
        __syncthreads();
    }

    const float scale = rsqrtf((float)C_);
#pragma unroll
    for (int nt = 0; nt < 24; nt++) {
        const int mat  = nt >> 3;
        const int ncol = ((nt & 7) << 3) + 2*q;
        unsigned* dst = (mat == 0) ? g_Q : (mat == 1) ? g_K : g_V;
        const float s = (mat == 0) ? scale : 1.f;
        long base = (row0 + r0 + g)*H_ + ncol;
        *(uint2*)(dst + base)        = make_uint2(f2tf32(acc[nt][0]*s), f2tf32(acc[nt][1]*s));
        *(uint2*)(dst + base + 8*H_) = make_uint2(f2tf32(acc[nt][2]*s), f2tf32(acc[nt][3]*s));
    }
}

// ---------------------------------------------------------------------------
// Flash attention, tf32 mma, cp.async double-buffered K/V (unchanged from R3;
// math value-identical to the R2 kernel that measured rel_err 2.8e-4).
// ---------------------------------------------------------------------------
#define QP 68
#define VP 72
#define KST (64*QP)
#define VST (64*VP)

__global__ __launch_bounds__(128) void flash_mma(float* __restrict__ out)
{
    extern __shared__ uint32_t smu[];
    uint32_t* Qs = smu;                  // [64][QP]
    uint32_t* Ps = smu + KST;            // [64][QP]
    uint32_t* Ks = smu + 2*KST;          // [2][64][QP]
    uint32_t* Vs = smu + 4*KST;          // [2][64][VP]

    const int tid  = threadIdx.x;
    const int lane = tid & 31;
    const int warp = tid >> 5;
    const int g    = lane >> 2;
    const int q    = lane & 3;
    const int r0   = warp << 4;
    const int b    = blockIdx.y;
    const int qt   = 63 - (int)blockIdx.x;
    const int q0   = qt << 6;

    const unsigned* Qg = g_Q + ((long)b*T_ + q0)*H_;
    const unsigned* Kg = g_K + (long)b*T_*H_;
    const unsigned* Vg = g_V + (long)b*T_*H_;

#pragma unroll
    for (int t = 0; t < 8; t++) {
        int idx4 = tid + t*128;
        int r  = idx4 >> 4;
        int c4 = (idx4 & 15) << 2;
        CPA16(smaddr(Qs + r*QP + c4), Qg + r*H_ + c4);
    }
    CP_COMMIT();

    auto issue_kv = [&](int kt, int st) {
        const long k0 = (long)(kt << 6);
#pragma unroll
        for (int t = 0; t < 8; t++) {
            int idx4 = tid + t*128;
            int r  = idx4 >> 4;
            int c4 = (idx4 & 15) << 2;
            CPA16(smaddr(Ks + st*KST + r*QP + c4), Kg + (k0 + r)*H_ + c4);
            CPA16(smaddr(Vs + st*VST + r*VP + c4), Vg + (k0 + r)*H_ + c4);
        }
    };
    issue_kv(0, 0); CP_COMMIT();

    float o[8][4];
#pragma unroll
    for (int j = 0; j < 8; j++) { o[j][0]=0.f; o[j][1]=0.f; o[j][2]=0.f; o[j][3]=0.f; }
    float m0 = -INFINITY, m1 = -INFINITY, l0 = 0.f, l1 = 0.f;

    for (int kt = 0; kt <= qt; kt++) {
        const int st = kt & 1;
        CP_WAIT0();
        __syncthreads();
        if (kt < qt) { issue_kv(kt + 1, st ^ 1); CP_COMMIT(); }

        const uint32_t* Kb = Ks + st*KST;
        const uint32_t* Vb = Vs + st*VST;

        float s[8][4];
#pragma unroll
        for (int j = 0; j < 8; j++) { s[j][0]=0.f; s[j][1]=0.f; s[j][2]=0.f; s[j][3]=0.f; }

#pragma unroll
        for (int h0 = 0; h0 < H_; h0 += 8) {
            uint32_t a0 = Qs[(r0+g  )*QP + h0 + q];
            uint32_t a1 = Qs[(r0+g+8)*QP + h0 + q];
            uint32_t a2 = Qs[(r0+g  )*QP + h0 + q + 4];
            uint32_t a3 = Qs[(r0+g+8)*QP + h0 + q + 4];
#pragma unroll
            for (int j = 0; j < 8; j++) {
                uint32_t b0 = Kb[(j*8+g)*QP + h0 + q];
                uint32_t b1 = Kb[(j*8+g)*QP + h0 + q + 4];
                mma_tf32(s[j], a0, a1, a2, a3, b0, b1);
            }
        }

        if (kt == qt) {
#pragma unroll
            for (int j = 0; j < 8; j++) {
                int c0 = j*8 + 2*q, c1 = c0 + 1;
                int ra = r0 + g,    rb = ra + 8;
                if (c0 > ra) s[j][0] = -INFINITY;
                if (c1 > ra) s[j][1] = -INFINITY;
                if (c0 > rb) s[j][2] = -INFINITY;
                if (c1 > rb) s[j][3] = -INFINITY;
            }
        }

        float tm0 = -INFINITY, tm1 = -INFINITY;
#pragma unroll
        for (int j = 0; j < 8; j++) {
            tm0 = fmaxf(tm0, fmaxf(s[j][0], s[j][1]));
            tm1 = fmaxf(tm1, fmaxf(s[j][2], s[j][3]));
        }
        tm0 = fmaxf(tm0, __shfl_xor_sync(0xffffffffu, tm0, 1));
        tm0 = fmaxf(tm0, __shfl_xor_sync(0xffffffffu, tm0, 2));
        tm1 = fmaxf(tm1, __shfl_xor_sync(0xffffffffu, tm1, 1));
        tm1 = fmaxf(tm1, __shfl_xor_sync(0xffffffffu, tm1, 2));

        float mn0 = fmaxf(m0, tm0), mn1 = fmaxf(m1, tm1);
        float al0 = __expf(m0 - mn0), al1 = __expf(m1 - mn1);
        m0 = mn0; m1 = mn1;

        float rs0 = 0.f, rs1 = 0.f;
#pragma unroll
        for (int j = 0; j < 8; j++) {
            float p0 = __expf(s[j][0] - mn0);
            float p1 = __expf(s[j][1] - mn0);
            float p2 = __expf(s[j][2] - mn1);
            float p3 = __expf(s[j][3] - mn1);
            rs0 += p0 + p1;
            rs1 += p2 + p3;
            int c = j*8 + 2*q;
            *(uint2*)(Ps + (r0+g  )*QP + c) = make_uint2(f2tf32(p0), f2tf32(p1));
            *(uint2*)(Ps + (r0+g+8)*QP + c) = make_uint2(f2tf32(p2), f2tf32(p3));
        }
        rs0 += __shfl_xor_sync(0xffffffffu, rs0, 1);
        rs0 += __shfl_xor_sync(0xffffffffu, rs0, 2);
        rs1 += __shfl_xor_sync(0xffffffffu, rs1, 1);
        rs1 += __shfl_xor_sync(0xffffffffu, rs1, 2);
        l0 = l0*al0 + rs0;
        l1 = l1*al1 + rs1;

#pragma unroll
        for (int j = 0; j < 8; j++) {
            o[j][0] *= al0; o[j][1] *= al0;
            o[j][2] *= al1; o[j][3] *= al1;
        }
        __syncwarp();

#pragma unroll
        for (int kk = 0; kk < 64; kk += 8) {
            uint32_t a0 = Ps[(r0+g  )*QP + kk + q];
            uint32_t a1 = Ps[(r0+g+8)*QP + kk + q];
            uint32_t a2 = Ps[(r0+g  )*QP + kk + q + 4];
            uint32_t a3 = Ps[(r0+g+8)*QP + kk + q + 4];
#pragma unroll
            for (int j = 0; j < 8; j++) {
                uint32_t b0 = Vb[(kk+q  )*VP + j*8 + g];
                uint32_t b1 = Vb[(kk+q+4)*VP + j*8 + g];
                mma_tf32(o[j], a0, a1, a2, a3, b0, b1);
            }
        }
    }

    float inv0 = 1.f / l0, inv1 = 1.f / l1;
    float* outb = out + ((long)b*T_ + q0)*H_;
#pragma unroll
    for (int j = 0; j < 8; j++) {
        int c = j*8 + 2*q;
        *(float2*)(outb + (r0+g  )*H_ + c) = make_float2(o[j][0]*inv0, o[j][1]*inv0);
        *(float2*)(outb + (r0+g+8)*H_ + c) = make_float2(o[j][2]*inv1, o[j][3]*inv1);
    }
}

// ---------------------------------------------------------------------------
extern "C" void kernel_launch(void* const* d_in, const int* in_sizes, int n_in,
                              void* d_out, int out_size)
{
    const float* x  = (const float*)d_in[0];
    const float* Wq = (const float*)d_in[1];
    const float* Wk = (const float*)d_in[2];
    const float* Wv = (const float*)d_in[3];
    float* out = (float*)d_out;

    wsplit_kernel<<<(3*C_*H_)/256, 256>>>(Wq, Wk, Wv);

    const int qkv_smem = (2*XS_SZ + 2*WS_SZ) * (int)sizeof(uint32_t);   // 137216 B
    cudaFuncSetAttribute(qkv_mma, cudaFuncAttributeMaxDynamicSharedMemorySize, qkv_smem);
    qkv_mma<<<(B_*T_)/128, 256, qkv_smem>>>(x);

    const int fl_smem = (4*KST + 2*VST) * (int)sizeof(uint32_t);        // 106496 B
    cudaFuncSetAttribute(flash_mma, cudaFuncAttributeMaxDynamicSharedMemorySize, fl_smem);
    dim3 grid(T_/64, B_);
    flash_mma<<<grid, 128, fl_smem>>>(out);
}